// round 1
// baseline (speedup 1.0000x reference)
#include <cuda_runtime.h>
#include <cstdint>

// ---------------------------------------------------------------------------
// SEE block: pointwise conv (GEMM1) -> depthwise temporal conv -> BN1 -> LIF1
//            -> linear (sparse over binary spikes) -> BN2 -> LIF2 -> +residual
// Shapes: B=64, T=1000, F=140, D=256, K=7, tau=2, v_th=1, hard reset.
// Output: (T,B,D) fp32.
// ---------------------------------------------------------------------------

#define B_  64
#define T_  1000
#define F_  140
#define D_  256
#define K_  7

// Scratch (no cudaMalloc allowed)
__device__ float    g_y[(size_t)B_ * T_ * D_];       // GEMM1 output, (B,T,D), 65.5 MB
__device__ unsigned g_mask[(size_t)T_ * B_ * 8];     // spike1 bitmask, (T,B,8 words), 2 MB
__device__ float    g_linT[D_ * D_];                 // lin_w transposed: [d][e]

// ---------------------------------------------------------------------------
// Kernel 0: transpose lin_w (e,d) -> linT (d,e)   (tiny: 256 KB)
// ---------------------------------------------------------------------------
__global__ void k_transpose(const float* __restrict__ w) {
    int d = blockIdx.x;      // 0..255
    int e = threadIdx.x;     // 0..255
    g_linT[d * D_ + e] = w[e * D_ + d];
}

// ---------------------------------------------------------------------------
// Kernel 1: GEMM1  y[m,n] = sum_k x[m,k] * pw_w[n,k]
//           M = B*T = 64000, N = D = 256, K = F = 140
// Tiles: BM=64, BN=64, BK=20, 256 threads, 4x4 microtile.
// ---------------------------------------------------------------------------
#define BM 64
#define BN 64
#define BK 20

__global__ __launch_bounds__(256) void k_gemm1(const float* __restrict__ x,
                                               const float* __restrict__ w) {
    __shared__ float As[BK][BM];
    __shared__ float Bs[BK][BN];

    const int tid = threadIdx.x;
    const int m0  = blockIdx.y * BM;
    const int n0  = blockIdx.x * BN;
    const int tm  = (tid >> 4) << 2;   // 0..60 step 4
    const int tn  = (tid & 15) << 2;   // 0..60 step 4

    float c[4][4] = {};

    for (int k0 = 0; k0 < F_; k0 += BK) {
        // load A tile (x) : As[k][m]
        #pragma unroll
        for (int i = tid; i < BM * BK; i += 256) {
            int m = i / BK, k = i - m * BK;
            As[k][m] = x[(size_t)(m0 + m) * F_ + k0 + k];
        }
        // load B tile (pw_w) : Bs[k][n]
        #pragma unroll
        for (int i = tid; i < BN * BK; i += 256) {
            int n = i / BK, k = i - n * BK;
            Bs[k][n] = w[(size_t)(n0 + n) * F_ + k0 + k];
        }
        __syncthreads();

        #pragma unroll
        for (int k = 0; k < BK; k++) {
            float4 a = *(const float4*)&As[k][tm];
            float4 b = *(const float4*)&Bs[k][tn];
            c[0][0] += a.x * b.x; c[0][1] += a.x * b.y; c[0][2] += a.x * b.z; c[0][3] += a.x * b.w;
            c[1][0] += a.y * b.x; c[1][1] += a.y * b.y; c[1][2] += a.y * b.z; c[1][3] += a.y * b.w;
            c[2][0] += a.z * b.x; c[2][1] += a.z * b.y; c[2][2] += a.z * b.z; c[2][3] += a.z * b.w;
            c[3][0] += a.w * b.x; c[3][1] += a.w * b.y; c[3][2] += a.w * b.z; c[3][3] += a.w * b.w;
        }
        __syncthreads();
    }

    #pragma unroll
    for (int i = 0; i < 4; i++) {
        float4 v = make_float4(c[i][0], c[i][1], c[i][2], c[i][3]);
        *(float4*)&g_y[(size_t)(m0 + tm + i) * D_ + n0 + tn] = v;
    }
}

// ---------------------------------------------------------------------------
// Kernel 2: depthwise conv (K=7, same pad) + bias + BN1 + LIF1 -> spike bitmask
// grid (64, 2) x 128 threads: one thread per (b, d) channel, serial over t.
// ---------------------------------------------------------------------------
__global__ __launch_bounds__(128) void k_lif1(const float* __restrict__ pw_b,
                                              const float* __restrict__ dw,
                                              const float* __restrict__ g1,
                                              const float* __restrict__ b1,
                                              const float* __restrict__ m1,
                                              const float* __restrict__ v1) {
    const int b    = blockIdx.x;
    const int d    = blockIdx.y * 128 + threadIdx.x;
    const int lane = threadIdx.x & 31;
    const int wid  = d >> 5;                 // global word index 0..7

    const float bias  = pw_b[d];
    float a[K_];
    #pragma unroll
    for (int k = 0; k < K_; k++) a[k] = dw[d * K_ + k];
    const float scale = g1[d] * rsqrtf(v1[d] + 1e-5f);
    const float shift = b1[d] - m1[d] * scale;

    const float* yp = g_y + (size_t)b * T_ * D_ + d;

    // window w0..w6 = conv input at tau-3 .. tau+3 (zero padded)
    float w0 = 0.f, w1 = 0.f, w2 = 0.f;
    float w3 = yp[0 * D_] + bias;
    float w4 = yp[1 * D_] + bias;
    float w5 = yp[2 * D_] + bias;
    float w6 = yp[3 * D_] + bias;

    float v = 0.f;

    for (int t0 = 0; t0 < T_; t0 += 8) {
        float f[8];
        #pragma unroll
        for (int j = 0; j < 8; j++) {
            int t = t0 + 4 + j;
            f[j] = (t < T_) ? (yp[(size_t)t * D_] + bias) : 0.f;
        }
        #pragma unroll
        for (int j = 0; j < 8; j++) {
            float u = w0 * a[0] + w1 * a[1] + w2 * a[2] + w3 * a[3]
                    + w4 * a[4] + w5 * a[5] + w6 * a[6];
            u = u * scale + shift;
            v = 0.5f * (v + u);
            bool s = (v >= 1.0f);
            unsigned bal = __ballot_sync(0xffffffffu, s);
            if (s) v = 0.f;
            if (lane == 0) g_mask[(size_t)(t0 + j) * (B_ * 8) + b * 8 + wid] = bal;
            w0 = w1; w1 = w2; w2 = w3; w3 = w4; w4 = w5; w5 = w6; w6 = f[j];
        }
    }
}

// ---------------------------------------------------------------------------
// Kernel 3: sparse linear over spike bitmask + BN2 + LIF2 + residual -> out
// grid (64, 2) x 128 threads: one thread per (b, e) channel, serial over t.
// Mask words staged through smem in chunks of 250 timesteps.
// ---------------------------------------------------------------------------
#define TCHUNK 250

__global__ __launch_bounds__(128) void k_lif2(const float* __restrict__ g2,
                                              const float* __restrict__ b2,
                                              const float* __restrict__ m2,
                                              const float* __restrict__ v2p,
                                              float* __restrict__ out) {
    __shared__ unsigned sm[TCHUNK * 8];

    const int b = blockIdx.x;
    const int e = blockIdx.y * 128 + threadIdx.x;

    const float scale = g2[e] * rsqrtf(v2p[e] + 1e-5f);
    const float shift = b2[e] - m2[e] * scale;
    const int      myw   = e >> 5;
    const unsigned mybit = 1u << (e & 31);

    float v = 0.f;

    for (int t0 = 0; t0 < T_; t0 += TCHUNK) {
        __syncthreads();
        for (int i = threadIdx.x; i < TCHUNK * 8; i += 128) {
            sm[i] = g_mask[(size_t)(t0 + (i >> 3)) * (B_ * 8) + b * 8 + (i & 7)];
        }
        __syncthreads();

        for (int tt = 0; tt < TCHUNK; tt++) {
            unsigned wds[8];
            #pragma unroll
            for (int i = 0; i < 8; i++) wds[i] = sm[tt * 8 + i];

            float acc = 0.f;
            #pragma unroll
            for (int i = 0; i < 8; i++) {
                unsigned wd = wds[i];
                while (wd) {
                    int bit = __ffs(wd) - 1;
                    wd &= wd - 1;
                    acc += g_linT[(size_t)(i * 32 + bit) * D_ + e];
                }
            }
            float res = (wds[myw] & mybit) ? 1.f : 0.f;

            float u = acc * scale + shift;
            v = 0.5f * (v + u);
            float s;
            if (v >= 1.0f) { s = 1.f; v = 0.f; } else { s = 0.f; }

            out[((size_t)(t0 + tt) * B_ + b) * D_ + e] = s + res;
        }
    }
}

// ---------------------------------------------------------------------------
// Launch
// inputs: 0:x 1:pw_w 2:pw_b 3:dw_w 4:bn1_g 5:bn1_b 6:bn1_m 7:bn1_v
//         8:lin_w 9:bn2_g 10:bn2_b 11:bn2_m 12:bn2_v
// ---------------------------------------------------------------------------
extern "C" void kernel_launch(void* const* d_in, const int* in_sizes, int n_in,
                              void* d_out, int out_size) {
    const float* x    = (const float*)d_in[0];
    const float* pw_w = (const float*)d_in[1];
    const float* pw_b = (const float*)d_in[2];
    const float* dw_w = (const float*)d_in[3];
    const float* g1   = (const float*)d_in[4];
    const float* b1   = (const float*)d_in[5];
    const float* m1   = (const float*)d_in[6];
    const float* v1   = (const float*)d_in[7];
    const float* linw = (const float*)d_in[8];
    const float* g2   = (const float*)d_in[9];
    const float* b2   = (const float*)d_in[10];
    const float* m2   = (const float*)d_in[11];
    const float* v2   = (const float*)d_in[12];
    float* out = (float*)d_out;

    k_transpose<<<D_, D_>>>(linw);

    dim3 gg(D_ / BN, (B_ * T_) / BM);          // (4, 1000)
    k_gemm1<<<gg, 256>>>(x, pw_w);

    dim3 g2d(B_, 2);
    k_lif1<<<g2d, 128>>>(pw_b, dw_w, g1, b1, m1, v1);
    k_lif2<<<g2d, 128>>>(g2, b2, m2, v2, out);
}

// round 2
// speedup vs baseline: 3.5560x; 3.5560x over previous
#include <cuda_runtime.h>
#include <cuda_bf16.h>
#include <cstdint>

// ---------------------------------------------------------------------------
// SEE block on GB300.
// GEMM1 (bf16 tensor cores) -> depthwise conv+BN+LIF1 (T-chunked speculative)
// -> sparse linear over spike bitmask + BN + LIF2 + residual (T-chunked).
// B=64, T=1000, F=140, D=256, K=7, tau=2, v_th=1, hard reset.
// ---------------------------------------------------------------------------

#define B_   64
#define T_   1000
#define F_   140
#define D_   256
#define K_   7
#define NCH  8          // T chunks
#define CLEN 125        // chunk length (8*125 = 1000)
#define WARM 32         // speculative warmup steps (0.5^32 contraction)

__device__ float    g_y[(size_t)B_ * T_ * D_];     // GEMM1 out, (B,T,D)
__device__ unsigned g_mask[(size_t)T_ * B_ * 8];   // spike1 bitmask (T,B,8)
__device__ float    g_linT[D_ * D_];               // lin_w transposed [d][e]

// ---------------------------------------------------------------------------
// transpose lin_w (e,d) -> (d,e)
// ---------------------------------------------------------------------------
__global__ void k_transpose(const float* __restrict__ w) {
    int d = blockIdx.x, e = threadIdx.x;
    g_linT[d * D_ + e] = w[e * D_ + d];
}

// ---------------------------------------------------------------------------
// GEMM1: y[m,n] = sum_k x[m,k] * w[n,k],  M=64000 N=256 K=140
// bf16 mma.sync m16n8k16, BM=128 BN=128 BK=16, 8 warps (2m x 4n), 9 k-steps.
// ---------------------------------------------------------------------------
__device__ __forceinline__ unsigned pack_bf16(float lo, float hi) {
    __nv_bfloat162 h = __floats2bfloat162_rn(lo, hi);
    return *reinterpret_cast<unsigned*>(&h);
}

__global__ __launch_bounds__(256) void k_gemm1(const float* __restrict__ x,
                                               const float* __restrict__ w) {
    __shared__ unsigned As[128 * 8];   // 128 rows x 16 bf16 (8 u32/row)
    __shared__ unsigned Bs[128 * 8];

    const int tid  = threadIdx.x;
    const int m0   = blockIdx.x * 128;
    const int n0   = blockIdx.y * 128;
    const int warp = tid >> 5, lane = tid & 31;
    const int wm   = warp >> 2;        // 0..1  (64 rows each)
    const int wn   = warp & 3;         // 0..3  (32 cols each)
    const int g    = lane >> 2, tig = lane & 3;

    float c[4][4][4];
    #pragma unroll
    for (int i = 0; i < 4; i++)
        #pragma unroll
        for (int j = 0; j < 4; j++)
            #pragma unroll
            for (int r = 0; r < 4; r++) c[i][j][r] = 0.f;

    for (int s = 0; s < 9; ++s) {
        const int k0 = s * 16;
        // stage A (x) : 512 float4, 2 per thread
        #pragma unroll
        for (int it = 0; it < 2; ++it) {
            int i = tid + it * 256;
            int row = i >> 2, q = i & 3;
            int k = k0 + q * 4;
            float4 f = make_float4(0.f, 0.f, 0.f, 0.f);
            if (k < F_) f = *(const float4*)&x[(size_t)(m0 + row) * F_ + k];
            As[row * 8 + q * 2]     = pack_bf16(f.x, f.y);
            As[row * 8 + q * 2 + 1] = pack_bf16(f.z, f.w);
        }
        // stage B (pw_w) : 512 float4, 2 per thread
        #pragma unroll
        for (int it = 0; it < 2; ++it) {
            int i = tid + it * 256;
            int row = i >> 2, q = i & 3;
            int k = k0 + q * 4;
            float4 f = make_float4(0.f, 0.f, 0.f, 0.f);
            if (k < F_) f = *(const float4*)&w[(size_t)(n0 + row) * F_ + k];
            Bs[row * 8 + q * 2]     = pack_bf16(f.x, f.y);
            Bs[row * 8 + q * 2 + 1] = pack_bf16(f.z, f.w);
        }
        __syncthreads();

        unsigned a[4][4], b[4][2];
        #pragma unroll
        for (int mi = 0; mi < 4; mi++) {
            int r = wm * 64 + mi * 16;
            a[mi][0] = As[(r + g) * 8 + tig];
            a[mi][1] = As[(r + g + 8) * 8 + tig];
            a[mi][2] = As[(r + g) * 8 + tig + 4];
            a[mi][3] = As[(r + g + 8) * 8 + tig + 4];
        }
        #pragma unroll
        for (int ni = 0; ni < 4; ni++) {
            int cb = wn * 32 + ni * 8;
            b[ni][0] = Bs[(cb + g) * 8 + tig];
            b[ni][1] = Bs[(cb + g) * 8 + tig + 4];
        }
        #pragma unroll
        for (int mi = 0; mi < 4; mi++)
            #pragma unroll
            for (int ni = 0; ni < 4; ni++) {
                asm volatile(
                    "mma.sync.aligned.m16n8k16.row.col.f32.bf16.bf16.f32 "
                    "{%0,%1,%2,%3}, {%4,%5,%6,%7}, {%8,%9}, {%0,%1,%2,%3};\n"
                    : "+f"(c[mi][ni][0]), "+f"(c[mi][ni][1]),
                      "+f"(c[mi][ni][2]), "+f"(c[mi][ni][3])
                    : "r"(a[mi][0]), "r"(a[mi][1]), "r"(a[mi][2]), "r"(a[mi][3]),
                      "r"(b[ni][0]), "r"(b[ni][1]));
            }
        __syncthreads();
    }

    // epilogue: (g,2tig),(g,2tig+1) / (g+8, ...) per m16n8 tile
    #pragma unroll
    for (int mi = 0; mi < 4; mi++) {
        int r0 = m0 + wm * 64 + mi * 16 + g;
        #pragma unroll
        for (int ni = 0; ni < 4; ni++) {
            int col = n0 + wn * 32 + ni * 8 + 2 * tig;
            *(float2*)&g_y[(size_t)r0 * D_ + col] =
                make_float2(c[mi][ni][0], c[mi][ni][1]);
            *(float2*)&g_y[(size_t)(r0 + 8) * D_ + col] =
                make_float2(c[mi][ni][2], c[mi][ni][3]);
        }
    }
}

// ---------------------------------------------------------------------------
// LIF1: depthwise conv (K=7 same pad) + bias + BN1 + LIF -> spike bitmask.
// grid (B, NCH, 2) x 128 thr; thread = one (b,d) channel, chunk of 125 t's
// with 32-step speculative warmup (v=0 start, 0.5x/step contraction).
// ---------------------------------------------------------------------------
__global__ __launch_bounds__(128) void k_lif1(const float* __restrict__ pw_b,
                                              const float* __restrict__ dw,
                                              const float* __restrict__ g1,
                                              const float* __restrict__ b1,
                                              const float* __restrict__ m1,
                                              const float* __restrict__ v1) {
    const int b    = blockIdx.x;
    const int ch   = blockIdx.y;
    const int d    = blockIdx.z * 128 + threadIdx.x;
    const int lane = threadIdx.x & 31;
    const int wid  = d >> 5;

    const float bias = pw_b[d];
    float a[K_];
    #pragma unroll
    for (int k = 0; k < K_; k++) a[k] = dw[d * K_ + k];
    const float scale = g1[d] * rsqrtf(v1[d] + 1e-5f);
    const float shift = b1[d] - m1[d] * scale;

    const float* yp = g_y + (size_t)b * T_ * D_ + d;

    const int tstart = ch * CLEN;
    const int ts     = (ch == 0) ? 0 : tstart - WARM;

    float w0, w1, w2, w3, w4, w5, w6;
    {
        float wv[7];
        #pragma unroll
        for (int j = 0; j < 7; j++) {
            int t = ts - 3 + j;
            wv[j] = (t >= 0 && t < T_) ? (yp[(size_t)t * D_] + bias) : 0.f;
        }
        w0 = wv[0]; w1 = wv[1]; w2 = wv[2]; w3 = wv[3];
        w4 = wv[4]; w5 = wv[5]; w6 = wv[6];
    }

    float v = 0.f;

    // warmup (no writes)
    for (int t = ts; t < tstart; ++t) {
        float u = w0 * a[0] + w1 * a[1] + w2 * a[2] + w3 * a[3]
                + w4 * a[4] + w5 * a[5] + w6 * a[6];
        u = u * scale + shift;
        v = 0.5f * (v + u);
        if (v >= 1.0f) v = 0.f;
        float nf = (t + 4 < T_) ? (yp[(size_t)(t + 4) * D_] + bias) : 0.f;
        w0 = w1; w1 = w2; w2 = w3; w3 = w4; w4 = w5; w5 = w6; w6 = nf;
    }

    // main chunk
    #pragma unroll 5
    for (int t = tstart; t < tstart + CLEN; ++t) {
        float u = w0 * a[0] + w1 * a[1] + w2 * a[2] + w3 * a[3]
                + w4 * a[4] + w5 * a[5] + w6 * a[6];
        u = u * scale + shift;
        v = 0.5f * (v + u);
        bool s = (v >= 1.0f);
        unsigned bal = __ballot_sync(0xffffffffu, s);
        if (s) v = 0.f;
        if (lane == 0) g_mask[(size_t)t * (B_ * 8) + b * 8 + wid] = bal;
        float nf = (t + 4 < T_) ? (yp[(size_t)(t + 4) * D_] + bias) : 0.f;
        w0 = w1; w1 = w2; w2 = w3; w3 = w4; w4 = w5; w5 = w6; w6 = nf;
    }
}

// ---------------------------------------------------------------------------
// LIF2: sparse linear over bitmask + BN2 + LIF + residual -> out (T,B,D).
// grid (B, NCH, 2) x 128 thr; masks staged in smem; fast path when no spikes.
// ---------------------------------------------------------------------------
__global__ __launch_bounds__(128) void k_lif2(const float* __restrict__ g2,
                                              const float* __restrict__ b2,
                                              const float* __restrict__ m2,
                                              const float* __restrict__ v2p,
                                              float* __restrict__ out) {
    __shared__ unsigned sm[(CLEN + WARM) * 8];

    const int b  = blockIdx.x;
    const int ch = blockIdx.y;
    const int e  = blockIdx.z * 128 + threadIdx.x;

    const int tstart = ch * CLEN;
    const int ts     = (ch == 0) ? 0 : tstart - WARM;
    const int nT     = tstart + CLEN - ts;

    for (int i = threadIdx.x; i < nT * 8; i += 128)
        sm[i] = g_mask[(size_t)(ts + (i >> 3)) * (B_ * 8) + b * 8 + (i & 7)];
    __syncthreads();

    const float scale = g2[e] * rsqrtf(v2p[e] + 1e-5f);
    const float shift = b2[e] - m2[e] * scale;
    const int      myw   = e >> 5;
    const unsigned mybit = 1u << (e & 31);

    float v = 0.f;

    for (int t = ts; t < tstart + CLEN; ++t) {
        const int o = (t - ts) * 8;
        uint4 p0 = *(const uint4*)&sm[o];
        uint4 p1 = *(const uint4*)&sm[o + 4];
        unsigned any = p0.x | p0.y | p0.z | p0.w | p1.x | p1.y | p1.z | p1.w;

        float acc = 0.f, res = 0.f;
        if (any) {
            unsigned wds[8] = {p0.x, p0.y, p0.z, p0.w, p1.x, p1.y, p1.z, p1.w};
            #pragma unroll
            for (int i = 0; i < 8; i++) {
                unsigned wd = wds[i];
                if (i == myw && (wd & mybit)) res = 1.f;
                while (wd) {
                    int bit = __ffs(wd) - 1;
                    wd &= wd - 1;
                    acc += g_linT[(size_t)(i * 32 + bit) * D_ + e];
                }
            }
        }

        float u = acc * scale + shift;
        v = 0.5f * (v + u);
        float sp = 0.f;
        if (v >= 1.0f) { sp = 1.f; v = 0.f; }

        if (t >= tstart)
            out[((size_t)t * B_ + b) * D_ + e] = sp + res;
    }
}

// ---------------------------------------------------------------------------
// inputs: 0:x 1:pw_w 2:pw_b 3:dw_w 4:bn1_g 5:bn1_b 6:bn1_m 7:bn1_v
//         8:lin_w 9:bn2_g 10:bn2_b 11:bn2_m 12:bn2_v
// ---------------------------------------------------------------------------
extern "C" void kernel_launch(void* const* d_in, const int* in_sizes, int n_in,
                              void* d_out, int out_size) {
    const float* x    = (const float*)d_in[0];
    const float* pw_w = (const float*)d_in[1];
    const float* pw_b = (const float*)d_in[2];
    const float* dw_w = (const float*)d_in[3];
    const float* g1   = (const float*)d_in[4];
    const float* b1   = (const float*)d_in[5];
    const float* m1   = (const float*)d_in[6];
    const float* v1   = (const float*)d_in[7];
    const float* linw = (const float*)d_in[8];
    const float* g2   = (const float*)d_in[9];
    const float* b2   = (const float*)d_in[10];
    const float* m2   = (const float*)d_in[11];
    const float* v2   = (const float*)d_in[12];
    float* out = (float*)d_out;

    k_transpose<<<D_, D_>>>(linw);

    dim3 gg((B_ * T_) / 128, D_ / 128);        // (500, 2)
    k_gemm1<<<gg, 256>>>(x, pw_w);

    dim3 gl(B_, NCH, 2);
    k_lif1<<<gl, 128>>>(pw_b, dw_w, g1, b1, m1, v1);
    k_lif2<<<gl, 128>>>(g2, b2, m2, v2, out);
}

// round 3
// speedup vs baseline: 4.6290x; 1.3017x over previous
#include <cuda_runtime.h>
#include <cuda_bf16.h>
#include <cstdint>

// ---------------------------------------------------------------------------
// SEE block on GB300.
// GEMM1 (bf16 mma.sync, + folded lin_w transpose) ->
// depthwise conv+BN+LIF1 (T-chunked speculative, folded constants) ->
// sparse linear over spike bitmask + BN + LIF2 + residual (chunk fast path).
// B=64, T=1000, F=140, D=256, K=7, tau=2, v_th=1, hard reset.
// ---------------------------------------------------------------------------

#define B_   64
#define T_   1000
#define F_   140
#define D_   256
#define K_   7
#define NCH  10         // T chunks
#define CLEN 100        // chunk length (10*100 = 1000)
#define WARM 16         // speculative warmup steps (0.5^16 ~ 1.5e-5 contraction)

__device__ float    g_y[(size_t)B_ * T_ * D_];     // GEMM1 out, (B,T,D)
__device__ unsigned g_mask[(size_t)T_ * B_ * 8];   // spike1 bitmask (T,B,8)
__device__ float    g_linT[D_ * D_];               // lin_w transposed [d][e]

// ---------------------------------------------------------------------------
// GEMM1: y[m,n] = sum_k x[m,k] * w[n,k],  M=64000 N=256 K=140
// bf16 mma.sync m16n8k16, BM=128 BN=128 BK=16, 8 warps (2m x 4n), 9 k-steps.
// First 256 blocks also transpose one row of lin_w into g_linT.
// ---------------------------------------------------------------------------
__device__ __forceinline__ unsigned pack_bf16(float lo, float hi) {
    __nv_bfloat162 h = __floats2bfloat162_rn(lo, hi);
    return *reinterpret_cast<unsigned*>(&h);
}

__global__ __launch_bounds__(256) void k_gemm1(const float* __restrict__ x,
                                               const float* __restrict__ w,
                                               const float* __restrict__ linw) {
    __shared__ unsigned As[128 * 8];   // 128 rows x 16 bf16 (8 u32/row)
    __shared__ unsigned Bs[128 * 8];

    const int tid  = threadIdx.x;
    const int m0   = blockIdx.x * 128;
    const int n0   = blockIdx.y * 128;

    // folded transpose: block (d, 0) for d<256 copies column d of lin_w
    if (blockIdx.y == 0 && blockIdx.x < D_) {
        int d = blockIdx.x;
        g_linT[d * D_ + tid] = linw[tid * D_ + d];
    }

    const int warp = tid >> 5, lane = tid & 31;
    const int wm   = warp >> 2;        // 0..1  (64 rows each)
    const int wn   = warp & 3;         // 0..3  (32 cols each)
    const int g    = lane >> 2, tig = lane & 3;

    float c[4][4][4];
    #pragma unroll
    for (int i = 0; i < 4; i++)
        #pragma unroll
        for (int j = 0; j < 4; j++)
            #pragma unroll
            for (int r = 0; r < 4; r++) c[i][j][r] = 0.f;

    for (int s = 0; s < 9; ++s) {
        const int k0 = s * 16;
        #pragma unroll
        for (int it = 0; it < 2; ++it) {
            int i = tid + it * 256;
            int row = i >> 2, q = i & 3;
            int k = k0 + q * 4;
            float4 f = make_float4(0.f, 0.f, 0.f, 0.f);
            if (k < F_) f = *(const float4*)&x[(size_t)(m0 + row) * F_ + k];
            As[row * 8 + q * 2]     = pack_bf16(f.x, f.y);
            As[row * 8 + q * 2 + 1] = pack_bf16(f.z, f.w);
        }
        #pragma unroll
        for (int it = 0; it < 2; ++it) {
            int i = tid + it * 256;
            int row = i >> 2, q = i & 3;
            int k = k0 + q * 4;
            float4 f = make_float4(0.f, 0.f, 0.f, 0.f);
            if (k < F_) f = *(const float4*)&w[(size_t)(n0 + row) * F_ + k];
            Bs[row * 8 + q * 2]     = pack_bf16(f.x, f.y);
            Bs[row * 8 + q * 2 + 1] = pack_bf16(f.z, f.w);
        }
        __syncthreads();

        unsigned a[4][4], b[4][2];
        #pragma unroll
        for (int mi = 0; mi < 4; mi++) {
            int r = wm * 64 + mi * 16;
            a[mi][0] = As[(r + g) * 8 + tig];
            a[mi][1] = As[(r + g + 8) * 8 + tig];
            a[mi][2] = As[(r + g) * 8 + tig + 4];
            a[mi][3] = As[(r + g + 8) * 8 + tig + 4];
        }
        #pragma unroll
        for (int ni = 0; ni < 4; ni++) {
            int cb = wn * 32 + ni * 8;
            b[ni][0] = Bs[(cb + g) * 8 + tig];
            b[ni][1] = Bs[(cb + g) * 8 + tig + 4];
        }
        #pragma unroll
        for (int mi = 0; mi < 4; mi++)
            #pragma unroll
            for (int ni = 0; ni < 4; ni++) {
                asm volatile(
                    "mma.sync.aligned.m16n8k16.row.col.f32.bf16.bf16.f32 "
                    "{%0,%1,%2,%3}, {%4,%5,%6,%7}, {%8,%9}, {%0,%1,%2,%3};\n"
                    : "+f"(c[mi][ni][0]), "+f"(c[mi][ni][1]),
                      "+f"(c[mi][ni][2]), "+f"(c[mi][ni][3])
                    : "r"(a[mi][0]), "r"(a[mi][1]), "r"(a[mi][2]), "r"(a[mi][3]),
                      "r"(b[ni][0]), "r"(b[ni][1]));
            }
        __syncthreads();
    }

    #pragma unroll
    for (int mi = 0; mi < 4; mi++) {
        int r0 = m0 + wm * 64 + mi * 16 + g;
        #pragma unroll
        for (int ni = 0; ni < 4; ni++) {
            int col = n0 + wn * 32 + ni * 8 + 2 * tig;
            *(float2*)&g_y[(size_t)r0 * D_ + col] =
                make_float2(c[mi][ni][0], c[mi][ni][1]);
            *(float2*)&g_y[(size_t)(r0 + 8) * D_ + col] =
                make_float2(c[mi][ni][2], c[mi][ni][3]);
        }
    }
}

// ---------------------------------------------------------------------------
// LIF1 step body: v' = fma(v, 0.5, base + sum ac_k * w_k)   (all consts folded)
// ---------------------------------------------------------------------------
template <bool GUARD>
__device__ __forceinline__ void lif1_main(const float* __restrict__ yp,
                                          const float* ac, float base,
                                          float& v, float& w0, float& w1,
                                          float& w2, float& w3, float& w4,
                                          float& w5, float& w6,
                                          int tstart, int b, int wid, int lane) {
    #pragma unroll 5
    for (int t = tstart; t < tstart + CLEN; ++t) {
        float acc = base;
        acc = fmaf(w0, ac[0], acc); acc = fmaf(w1, ac[1], acc);
        acc = fmaf(w2, ac[2], acc); acc = fmaf(w3, ac[3], acc);
        acc = fmaf(w4, ac[4], acc); acc = fmaf(w5, ac[5], acc);
        acc = fmaf(w6, ac[6], acc);
        v = fmaf(v, 0.5f, acc);
        bool s = (v >= 1.0f);
        unsigned bal = __ballot_sync(0xffffffffu, s);
        if (s) v = 0.f;
        if (lane == 0) g_mask[(size_t)t * (B_ * 8) + b * 8 + wid] = bal;
        float nf;
        if (GUARD) nf = (t + 4 < T_) ? yp[(size_t)(t + 4) * D_] : 0.f;
        else       nf = yp[(size_t)(t + 4) * D_];
        w0 = w1; w1 = w2; w2 = w3; w3 = w4; w4 = w5; w5 = w6; w6 = nf;
    }
}

__global__ __launch_bounds__(128) void k_lif1(const float* __restrict__ pw_b,
                                              const float* __restrict__ dw,
                                              const float* __restrict__ g1,
                                              const float* __restrict__ b1,
                                              const float* __restrict__ m1,
                                              const float* __restrict__ v1) {
    const int b    = blockIdx.x;
    const int ch   = blockIdx.y;
    const int d    = blockIdx.z * 128 + threadIdx.x;
    const int lane = threadIdx.x & 31;
    const int wid  = d >> 5;

    const float bias  = pw_b[d];
    const float scale = g1[d] * rsqrtf(v1[d] + 1e-5f);
    const float shift = b1[d] - m1[d] * scale;

    float ac[K_];
    float suma = 0.f;
    #pragma unroll
    for (int k = 0; k < K_; k++) {
        float a = dw[d * K_ + k];
        suma += a;
        ac[k] = 0.5f * scale * a;
    }
    // v' = 0.5 v + 0.5*(scale*(conv(y)+bias*suma) + shift)
    const float base = 0.5f * (scale * bias * suma + shift);

    const float* yp = g_y + (size_t)b * T_ * D_ + d;

    const int tstart = ch * CLEN;
    const int ts     = (ch == 0) ? 0 : tstart - WARM;

    float w0, w1, w2, w3, w4, w5, w6;
    {
        float wv[7];
        #pragma unroll
        for (int j = 0; j < 7; j++) {
            int t = ts - 3 + j;
            wv[j] = (t >= 0 && t < T_) ? yp[(size_t)t * D_] : 0.f;
        }
        w0 = wv[0]; w1 = wv[1]; w2 = wv[2]; w3 = wv[3];
        w4 = wv[4]; w5 = wv[5]; w6 = wv[6];
    }

    float v = 0.f;

    // warmup (no writes); t+4 <= tstart+3 < T_ always here
    for (int t = ts; t < tstart; ++t) {
        float acc = base;
        acc = fmaf(w0, ac[0], acc); acc = fmaf(w1, ac[1], acc);
        acc = fmaf(w2, ac[2], acc); acc = fmaf(w3, ac[3], acc);
        acc = fmaf(w4, ac[4], acc); acc = fmaf(w5, ac[5], acc);
        acc = fmaf(w6, ac[6], acc);
        v = fmaf(v, 0.5f, acc);
        if (v >= 1.0f) v = 0.f;
        float nf = yp[(size_t)(t + 4) * D_];
        w0 = w1; w1 = w2; w2 = w3; w3 = w4; w4 = w5; w5 = w6; w6 = nf;
    }

    if (ch == NCH - 1)
        lif1_main<true >(yp, ac, base, v, w0, w1, w2, w3, w4, w5, w6,
                         tstart, b, wid, lane);
    else
        lif1_main<false>(yp, ac, base, v, w0, w1, w2, w3, w4, w5, w6,
                         tstart, b, wid, lane);
}

// ---------------------------------------------------------------------------
// LIF2: sparse linear over bitmask + BN2 + LIF + residual -> out (T,B,D).
// Chunk-level fast path: if no spikes in the whole staged window and the BN
// fixpoint (shift) is below threshold, every output in the chunk is 0.
// ---------------------------------------------------------------------------
__global__ __launch_bounds__(128) void k_lif2(const float* __restrict__ g2,
                                              const float* __restrict__ b2,
                                              const float* __restrict__ m2,
                                              const float* __restrict__ v2p,
                                              float* __restrict__ out) {
    __shared__ unsigned sm[(CLEN + WARM) * 8];
    __shared__ unsigned s_any;

    const int b  = blockIdx.x;
    const int ch = blockIdx.y;
    const int e  = blockIdx.z * 128 + threadIdx.x;

    const int tstart = ch * CLEN;
    const int ts     = (ch == 0) ? 0 : tstart - WARM;
    const int nT     = tstart + CLEN - ts;

    if (threadIdx.x == 0) s_any = 0u;
    __syncthreads();

    unsigned loc = 0u;
    for (int i = threadIdx.x; i < nT * 8; i += 128) {
        unsigned w = g_mask[(size_t)(ts + (i >> 3)) * (B_ * 8) + b * 8 + (i & 7)];
        sm[i] = w;
        loc |= w;
    }
    if (loc) atomicOr(&s_any, loc);
    __syncthreads();

    const float scale = g2[e] * rsqrtf(v2p[e] + 1e-5f);
    const float shift = b2[e] - m2[e] * scale;

    float* op = out + (size_t)tstart * (B_ * D_) + (size_t)b * D_ + e;

    if (s_any == 0u) {
        if (shift < 1.0f) {
            // provably spike-free chunk: all outputs zero
            #pragma unroll 10
            for (int j = 0; j < CLEN; ++j)
                op[(size_t)j * (B_ * D_)] = 0.f;
        } else {
            // no input spikes, constant drive; run bare recurrence
            const int n = tstart - ts;
            float v = shift * (1.f - __int_as_float((127 - n) << 23));
            const float hs = 0.5f * shift;
            #pragma unroll 10
            for (int j = 0; j < CLEN; ++j) {
                v = fmaf(v, 0.5f, hs);
                float sp = 0.f;
                if (v >= 1.0f) { sp = 1.f; v = 0.f; }
                op[(size_t)j * (B_ * D_)] = sp;
            }
        }
        return;
    }

    // slow path: spikes present somewhere in the window
    const int      myw   = e >> 5;
    const unsigned mybit = 1u << (e & 31);
    float v = 0.f;

    for (int t = ts; t < tstart + CLEN; ++t) {
        const int o = (t - ts) * 8;
        uint4 p0 = *(const uint4*)&sm[o];
        uint4 p1 = *(const uint4*)&sm[o + 4];
        unsigned any = p0.x | p0.y | p0.z | p0.w | p1.x | p1.y | p1.z | p1.w;

        float acc = 0.f, res = 0.f;
        if (any) {
            unsigned wds[8] = {p0.x, p0.y, p0.z, p0.w, p1.x, p1.y, p1.z, p1.w};
            #pragma unroll
            for (int i = 0; i < 8; i++) {
                unsigned wd = wds[i];
                if (i == myw && (wd & mybit)) res = 1.f;
                while (wd) {
                    int bit = __ffs(wd) - 1;
                    wd &= wd - 1;
                    acc += g_linT[(size_t)(i * 32 + bit) * D_ + e];
                }
            }
        }

        float u = fmaf(acc, scale, shift);
        v = 0.5f * (v + u);
        float sp = 0.f;
        if (v >= 1.0f) { sp = 1.f; v = 0.f; }

        if (t >= tstart)
            out[((size_t)t * B_ + b) * D_ + e] = sp + res;
    }
}

// ---------------------------------------------------------------------------
// inputs: 0:x 1:pw_w 2:pw_b 3:dw_w 4:bn1_g 5:bn1_b 6:bn1_m 7:bn1_v
//         8:lin_w 9:bn2_g 10:bn2_b 11:bn2_m 12:bn2_v
// ---------------------------------------------------------------------------
extern "C" void kernel_launch(void* const* d_in, const int* in_sizes, int n_in,
                              void* d_out, int out_size) {
    const float* x    = (const float*)d_in[0];
    const float* pw_w = (const float*)d_in[1];
    const float* pw_b = (const float*)d_in[2];
    const float* dw_w = (const float*)d_in[3];
    const float* g1   = (const float*)d_in[4];
    const float* b1   = (const float*)d_in[5];
    const float* m1   = (const float*)d_in[6];
    const float* v1   = (const float*)d_in[7];
    const float* linw = (const float*)d_in[8];
    const float* g2   = (const float*)d_in[9];
    const float* b2   = (const float*)d_in[10];
    const float* m2   = (const float*)d_in[11];
    const float* v2   = (const float*)d_in[12];
    float* out = (float*)d_out;

    dim3 gg((B_ * T_) / 128, D_ / 128);        // (500, 2)
    k_gemm1<<<gg, 256>>>(x, pw_w, linw);

    dim3 gl(B_, NCH, 2);
    k_lif1<<<gl, 128>>>(pw_b, dw_w, g1, b1, m1, v1);
    k_lif2<<<gl, 128>>>(g2, b2, m2, v2, out);
}

// round 4
// speedup vs baseline: 6.7374x; 1.4555x over previous
#include <cuda_runtime.h>
#include <cuda_bf16.h>
#include <cstdint>

// ---------------------------------------------------------------------------
// SEE block on GB300.
// GEMM1 (bf16 mma.sync, double-buffered reg-prefetch pipeline, folded lin_w
// transpose) -> fused [depthwise conv+BN+LIF1 -> sparse linear+BN+LIF2+res]
// with spike masks staged entirely in smem (T-chunked speculative LIF).
// B=64, T=1000, F=140, D=256, K=7, tau=2, v_th=1, hard reset.
// ---------------------------------------------------------------------------

#define B_    64
#define T_    1000
#define F_    140
#define D_    256
#define K_    7
#define NCH   10        // T chunks
#define CLEN  100       // chunk length
#define WARM1 16        // lif1 speculative warmup
#define WARM2 16        // lif2 speculative warmup (masks produced locally)
#define SMT   (CLEN + WARM2)   // mask rows held in smem

__device__ float g_y[(size_t)B_ * T_ * D_];     // GEMM1 out, (B,T,D)
__device__ float g_linT[D_ * D_];               // lin_w transposed [d][e]

// ---------------------------------------------------------------------------
// GEMM1: y[m,n] = sum_k x[m,k] * w[n,k],  M=64000 N=256 K=140
// bf16 mma.sync m16n8k16, BM=128 BN=128 BK=16, 8 warps (2m x 4n), 9 k-steps.
// Register-prefetch + double-buffered smem, 1 sync/step, conflict-free LDS
// (row stride 12 u32). First 256 blocks also transpose lin_w into g_linT.
// ---------------------------------------------------------------------------
#define ASTRIDE 12

__device__ __forceinline__ unsigned pack_bf16(float lo, float hi) {
    __nv_bfloat162 h = __floats2bfloat162_rn(lo, hi);
    return *reinterpret_cast<unsigned*>(&h);
}

__global__ __launch_bounds__(256) void k_gemm1(const float* __restrict__ x,
                                               const float* __restrict__ w,
                                               const float* __restrict__ linw) {
    __shared__ unsigned As[2][128 * ASTRIDE];
    __shared__ unsigned Bs[2][128 * ASTRIDE];

    const int tid = threadIdx.x;
    const int m0  = blockIdx.x * 128;
    const int n0  = blockIdx.y * 128;

    // folded transpose of lin_w
    if (blockIdx.y == 0 && blockIdx.x < D_) {
        int d = blockIdx.x;
        g_linT[d * D_ + tid] = linw[tid * D_ + d];
    }

    const int warp = tid >> 5, lane = tid & 31;
    const int wm   = warp >> 2;        // 0..1 (64 rows)
    const int wn   = warp & 3;         // 0..3 (32 cols)
    const int g    = lane >> 2, tig = lane & 3;

    const int row0 = tid >> 2, q0 = tid & 3;           // staging coords, it=0
    const int row1 = (tid + 256) >> 2, q1 = tid & 3;   // it=1

    float4 pa[2], pb[2];

    auto ld_tiles = [&](int s) {
        const int k0 = s * 16;
        {
            int k = k0 + q0 * 4;
            pa[0] = (k < F_) ? *(const float4*)&x[(size_t)(m0 + row0) * F_ + k]
                             : make_float4(0.f, 0.f, 0.f, 0.f);
            pb[0] = (k < F_) ? *(const float4*)&w[(size_t)(n0 + row0) * F_ + k]
                             : make_float4(0.f, 0.f, 0.f, 0.f);
        }
        {
            int k = k0 + q1 * 4;
            pa[1] = (k < F_) ? *(const float4*)&x[(size_t)(m0 + row1) * F_ + k]
                             : make_float4(0.f, 0.f, 0.f, 0.f);
            pb[1] = (k < F_) ? *(const float4*)&w[(size_t)(n0 + row1) * F_ + k]
                             : make_float4(0.f, 0.f, 0.f, 0.f);
        }
    };
    auto st_tiles = [&](int buf) {
        As[buf][row0 * ASTRIDE + q0 * 2]     = pack_bf16(pa[0].x, pa[0].y);
        As[buf][row0 * ASTRIDE + q0 * 2 + 1] = pack_bf16(pa[0].z, pa[0].w);
        As[buf][row1 * ASTRIDE + q1 * 2]     = pack_bf16(pa[1].x, pa[1].y);
        As[buf][row1 * ASTRIDE + q1 * 2 + 1] = pack_bf16(pa[1].z, pa[1].w);
        Bs[buf][row0 * ASTRIDE + q0 * 2]     = pack_bf16(pb[0].x, pb[0].y);
        Bs[buf][row0 * ASTRIDE + q0 * 2 + 1] = pack_bf16(pb[0].z, pb[0].w);
        Bs[buf][row1 * ASTRIDE + q1 * 2]     = pack_bf16(pb[1].x, pb[1].y);
        Bs[buf][row1 * ASTRIDE + q1 * 2 + 1] = pack_bf16(pb[1].z, pb[1].w);
    };

    float c[4][4][4];
    #pragma unroll
    for (int i = 0; i < 4; i++)
        #pragma unroll
        for (int j = 0; j < 4; j++)
            #pragma unroll
            for (int r = 0; r < 4; r++) c[i][j][r] = 0.f;

    ld_tiles(0);
    st_tiles(0);
    __syncthreads();

    int p = 0;
    for (int s = 0; s < 9; ++s) {
        if (s < 8) ld_tiles(s + 1);          // LDG prefetch (overlaps below)

        unsigned a[4][4], b[4][2];
        #pragma unroll
        for (int mi = 0; mi < 4; mi++) {
            int r = wm * 64 + mi * 16;
            a[mi][0] = As[p][(r + g) * ASTRIDE + tig];
            a[mi][1] = As[p][(r + g + 8) * ASTRIDE + tig];
            a[mi][2] = As[p][(r + g) * ASTRIDE + tig + 4];
            a[mi][3] = As[p][(r + g + 8) * ASTRIDE + tig + 4];
        }
        #pragma unroll
        for (int ni = 0; ni < 4; ni++) {
            int cb = wn * 32 + ni * 8;
            b[ni][0] = Bs[p][(cb + g) * ASTRIDE + tig];
            b[ni][1] = Bs[p][(cb + g) * ASTRIDE + tig + 4];
        }

        #pragma unroll
        for (int mi = 0; mi < 4; mi++)
            #pragma unroll
            for (int ni = 0; ni < 4; ni++) {
                asm volatile(
                    "mma.sync.aligned.m16n8k16.row.col.f32.bf16.bf16.f32 "
                    "{%0,%1,%2,%3}, {%4,%5,%6,%7}, {%8,%9}, {%0,%1,%2,%3};\n"
                    : "+f"(c[mi][ni][0]), "+f"(c[mi][ni][1]),
                      "+f"(c[mi][ni][2]), "+f"(c[mi][ni][3])
                    : "r"(a[mi][0]), "r"(a[mi][1]), "r"(a[mi][2]), "r"(a[mi][3]),
                      "r"(b[ni][0]), "r"(b[ni][1]));
            }

        if (s < 8) st_tiles(1 - p);          // stash next tile
        __syncthreads();
        p ^= 1;
    }

    #pragma unroll
    for (int mi = 0; mi < 4; mi++) {
        int r0 = m0 + wm * 64 + mi * 16 + g;
        #pragma unroll
        for (int ni = 0; ni < 4; ni++) {
            int col = n0 + wn * 32 + ni * 8 + 2 * tig;
            *(float2*)&g_y[(size_t)r0 * D_ + col] =
                make_float2(c[mi][ni][0], c[mi][ni][1]);
            *(float2*)&g_y[(size_t)(r0 + 8) * D_ + col] =
                make_float2(c[mi][ni][2], c[mi][ni][3]);
        }
    }
}

// ---------------------------------------------------------------------------
// Fused LIF: phase 1 = depthwise conv(K=7)+BN1+LIF1 -> spike masks in smem,
//            phase 2 = sparse linear+BN2+LIF2+residual -> out.
// grid (B, NCH) x 256 threads (thread = channel d, then channel e).
// ---------------------------------------------------------------------------
template <bool GUARD>
__device__ __forceinline__ void lif1_main(const float* __restrict__ yp,
                                          const float* ac, float base,
                                          float& v, float& w0, float& w1,
                                          float& w2, float& w3, float& w4,
                                          float& w5, float& w6,
                                          int ts2, int tend, unsigned* sm,
                                          unsigned& locOr, int warp, int lane) {
    #pragma unroll 4
    for (int t = ts2; t < tend; ++t) {
        float acc = base;
        acc = fmaf(w0, ac[0], acc); acc = fmaf(w1, ac[1], acc);
        acc = fmaf(w2, ac[2], acc); acc = fmaf(w3, ac[3], acc);
        acc = fmaf(w4, ac[4], acc); acc = fmaf(w5, ac[5], acc);
        acc = fmaf(w6, ac[6], acc);
        v = fmaf(v, 0.5f, acc);
        bool s = (v >= 1.0f);
        unsigned bal = __ballot_sync(0xffffffffu, s);
        if (s) v = 0.f;
        if (lane == 0) { sm[(t - ts2) * 8 + warp] = bal; locOr |= bal; }
        float nf;
        if (GUARD) nf = (t + 4 < T_) ? yp[(size_t)(t + 4) * D_] : 0.f;
        else       nf = yp[(size_t)(t + 4) * D_];
        w0 = w1; w1 = w2; w2 = w3; w3 = w4; w4 = w5; w5 = w6; w6 = nf;
    }
}

__global__ __launch_bounds__(256) void k_lif(const float* __restrict__ pw_b,
                                             const float* __restrict__ dw,
                                             const float* __restrict__ g1,
                                             const float* __restrict__ b1,
                                             const float* __restrict__ m1,
                                             const float* __restrict__ v1,
                                             const float* __restrict__ g2,
                                             const float* __restrict__ b2,
                                             const float* __restrict__ m2,
                                             const float* __restrict__ v2p,
                                             float* __restrict__ out) {
    __shared__ unsigned sm[SMT * 8];
    __shared__ unsigned s_any;

    const int b    = blockIdx.x;
    const int ch   = blockIdx.y;
    const int d    = threadIdx.x;          // phase-1 channel; phase-2 e == d
    const int lane = d & 31;
    const int warp = d >> 5;

    const int tstart = ch * CLEN;
    const int tend   = tstart + CLEN;
    const int ts2    = (ch == 0) ? 0 : tstart - WARM2;   // mask window start
    const int ts1    = (ch == 0) ? 0 : ts2 - WARM1;      // lif1 sim start

    if (d == 0) s_any = 0u;

    // ---- phase 1: LIF1 ----
    {
        const float bias  = pw_b[d];
        const float scale = g1[d] * rsqrtf(v1[d] + 1e-5f);
        const float shift = b1[d] - m1[d] * scale;

        float ac[K_];
        float suma = 0.f;
        #pragma unroll
        for (int k = 0; k < K_; k++) {
            float a = dw[d * K_ + k];
            suma += a;
            ac[k] = 0.5f * scale * a;
        }
        const float base = 0.5f * (scale * bias * suma + shift);

        const float* yp = g_y + (size_t)b * T_ * D_ + d;

        float w0, w1, w2, w3, w4, w5, w6;
        {
            float wv[7];
            #pragma unroll
            for (int j = 0; j < 7; j++) {
                int t = ts1 - 3 + j;
                wv[j] = (t >= 0) ? yp[(size_t)t * D_] : 0.f;  // upper bound safe
            }
            w0 = wv[0]; w1 = wv[1]; w2 = wv[2]; w3 = wv[3];
            w4 = wv[4]; w5 = wv[5]; w6 = wv[6];
        }

        float v = 0.f;
        // lif1 speculative warmup [ts1, ts2): no mask writes (empty for ch 0)
        for (int t = ts1; t < ts2; ++t) {
            float acc = base;
            acc = fmaf(w0, ac[0], acc); acc = fmaf(w1, ac[1], acc);
            acc = fmaf(w2, ac[2], acc); acc = fmaf(w3, ac[3], acc);
            acc = fmaf(w4, ac[4], acc); acc = fmaf(w5, ac[5], acc);
            acc = fmaf(w6, ac[6], acc);
            v = fmaf(v, 0.5f, acc);
            if (v >= 1.0f) v = 0.f;
            float nf = yp[(size_t)(t + 4) * D_];
            w0 = w1; w1 = w2; w2 = w3; w3 = w4; w4 = w5; w5 = w6; w6 = nf;
        }

        unsigned locOr = 0u;
        if (ch == NCH - 1)
            lif1_main<true >(yp, ac, base, v, w0, w1, w2, w3, w4, w5, w6,
                             ts2, tend, sm, locOr, warp, lane);
        else
            lif1_main<false>(yp, ac, base, v, w0, w1, w2, w3, w4, w5, w6,
                             ts2, tend, sm, locOr, warp, lane);

        if (lane == 0 && locOr) atomicOr(&s_any, locOr);
    }
    __syncthreads();

    // ---- phase 2: LIF2 ----
    const int e = d;
    const float scale2 = g2[e] * rsqrtf(v2p[e] + 1e-5f);
    const float shift2 = b2[e] - m2[e] * scale2;

    float* op = out + (size_t)tstart * (B_ * D_) + (size_t)b * D_ + e;

    if (s_any == 0u) {
        if (shift2 < 1.0f) {
            // provably spike-free chunk
            #pragma unroll 10
            for (int j = 0; j < CLEN; ++j)
                op[(size_t)j * (B_ * D_)] = 0.f;
        } else {
            // constant drive, explicit warmup + recurrence
            float v = 0.f;
            const float hs = 0.5f * shift2;
            for (int j = 0; j < tstart - ts2; ++j) {
                v = fmaf(v, 0.5f, hs);
                if (v >= 1.0f) v = 0.f;
            }
            #pragma unroll 10
            for (int j = 0; j < CLEN; ++j) {
                v = fmaf(v, 0.5f, hs);
                float sp = 0.f;
                if (v >= 1.0f) { sp = 1.f; v = 0.f; }
                op[(size_t)j * (B_ * D_)] = sp;
            }
        }
        return;
    }

    // slow path: spikes somewhere in the window
    const int      myw   = e >> 5;
    const unsigned mybit = 1u << (e & 31);
    float v = 0.f;

    for (int t = ts2; t < tend; ++t) {
        const int o = (t - ts2) * 8;
        uint4 p0 = *(const uint4*)&sm[o];
        uint4 p1 = *(const uint4*)&sm[o + 4];
        unsigned any = p0.x | p0.y | p0.z | p0.w | p1.x | p1.y | p1.z | p1.w;

        float acc = 0.f, res = 0.f;
        if (any) {
            unsigned wds[8] = {p0.x, p0.y, p0.z, p0.w, p1.x, p1.y, p1.z, p1.w};
            #pragma unroll
            for (int i = 0; i < 8; i++) {
                unsigned wd = wds[i];
                if (i == myw && (wd & mybit)) res = 1.f;
                while (wd) {
                    int bit = __ffs(wd) - 1;
                    wd &= wd - 1;
                    acc += g_linT[(size_t)(i * 32 + bit) * D_ + e];
                }
            }
        }

        float u = fmaf(acc, scale2, shift2);
        v = 0.5f * (v + u);
        float sp = 0.f;
        if (v >= 1.0f) { sp = 1.f; v = 0.f; }

        if (t >= tstart)
            out[((size_t)t * B_ + b) * D_ + e] = sp + res;
    }
}

// ---------------------------------------------------------------------------
// inputs: 0:x 1:pw_w 2:pw_b 3:dw_w 4:bn1_g 5:bn1_b 6:bn1_m 7:bn1_v
//         8:lin_w 9:bn2_g 10:bn2_b 11:bn2_m 12:bn2_v
// ---------------------------------------------------------------------------
extern "C" void kernel_launch(void* const* d_in, const int* in_sizes, int n_in,
                              void* d_out, int out_size) {
    const float* x    = (const float*)d_in[0];
    const float* pw_w = (const float*)d_in[1];
    const float* pw_b = (const float*)d_in[2];
    const float* dw_w = (const float*)d_in[3];
    const float* g1   = (const float*)d_in[4];
    const float* b1   = (const float*)d_in[5];
    const float* m1   = (const float*)d_in[6];
    const float* v1   = (const float*)d_in[7];
    const float* linw = (const float*)d_in[8];
    const float* g2   = (const float*)d_in[9];
    const float* b2   = (const float*)d_in[10];
    const float* m2   = (const float*)d_in[11];
    const float* v2   = (const float*)d_in[12];
    float* out = (float*)d_out;

    dim3 gg((B_ * T_) / 128, D_ / 128);        // (500, 2)
    k_gemm1<<<gg, 256>>>(x, pw_w, linw);

    dim3 gl(B_, NCH);
    k_lif<<<gl, 256>>>(pw_b, dw_w, g1, b1, m1, v1, g2, b2, m2, v2, out);
}